// round 2
// baseline (speedup 1.0000x reference)
#include <cuda_runtime.h>
#include <cuda_bf16.h>
#include <cstdint>

// DistMult edge scoring:
//   out[e] = sigmoid( sum_d h[src[e]][d] * W[rel[e]][d] * h[dst[e]][d] )
// E = 1,500,000 edges, D = 128, N = 100,000 nodes, R = 6 relations.
//
// NOTE: indices are int32 (JAX default x64-disabled downgrades the requested
// int64 to int32). Reading them as int64 was the R1 illegal-access bug.
//
// Layout: one warp per edge. Lane l handles float4 chunk l of the D=128 row
// (32 lanes x 4 floats = 128). h gathers are coalesced 512B per operand per
// warp and mostly L2 hits (h = 51.2 MB fits in L2). W (3 KB) lives in shared.
// Index arrays / output are streamed with evict-first hints.

#define D        128
#define N_RELS   6
#define TPB      256               // 8 warps (= 8 edges) per block

__global__ __launch_bounds__(TPB) void distmult_kernel(
    const float* __restrict__ h,
    const float* __restrict__ W,
    const int* __restrict__ src,
    const int* __restrict__ dst,
    const int* __restrict__ rel,
    float* __restrict__ out,
    int E)
{
    __shared__ float sW[N_RELS * D];   // 3 KB

    // Stage W into shared (6*128 = 768 floats).
    for (int i = threadIdx.x; i < N_RELS * D; i += TPB)
        sW[i] = W[i];
    __syncthreads();

    const int warp_in_block = threadIdx.x >> 5;
    const int lane          = threadIdx.x & 31;
    const int e = blockIdx.x * (TPB / 32) + warp_in_block;
    if (e >= E) return;

    // Per-edge indices: same address across the warp -> single broadcast load.
    // Streaming (evict-first): don't let 18 MB of indices evict h from L2.
    const int s = __ldcs(&src[e]);
    const int d = __ldcs(&dst[e]);
    const int r = __ldcs(&rel[e]);

    // Coalesced float4 gathers: 32 lanes * 16B = full 512B row per operand.
    const float4 u  = __ldg((const float4*)(h + (size_t)s * D) + lane);
    const float4 v  = __ldg((const float4*)(h + (size_t)d * D) + lane);
    const float4 wr = *((const float4*)(sW + r * D) + lane);

    float acc = u.x * wr.x * v.x
              + u.y * wr.y * v.y
              + u.z * wr.z * v.z
              + u.w * wr.w * v.w;

    // Warp-wide sum.
    #pragma unroll
    for (int off = 16; off > 0; off >>= 1)
        acc += __shfl_xor_sync(0xFFFFFFFFu, acc, off);

    if (lane == 0) {
        float sig = 1.0f / (1.0f + __expf(-acc));
        __stcs(&out[e], sig);   // streaming store
    }
}

extern "C" void kernel_launch(void* const* d_in, const int* in_sizes, int n_in,
                              void* d_out, int out_size)
{
    const float* h   = (const float*)d_in[0];
    const float* W   = (const float*)d_in[1];
    const int*   src = (const int*)d_in[2];
    const int*   dst = (const int*)d_in[3];
    const int*   rel = (const int*)d_in[4];
    float* out = (float*)d_out;

    const int E = in_sizes[2];                 // number of edges
    const int edges_per_block = TPB / 32;      // 8
    const int blocks = (E + edges_per_block - 1) / edges_per_block;

    distmult_kernel<<<blocks, TPB>>>(h, W, src, dst, rel, out, E);
}

// round 3
// speedup vs baseline: 2.1421x; 2.1421x over previous
#include <cuda_runtime.h>
#include <cuda_bf16.h>
#include <cstdint>

// DistMult edge scoring:
//   out[e] = sigmoid( sum_d h[src[e]][d] * W[rel[e]][d] * h[dst[e]][d] )
// E = 1,500,000, D = 128, N = 100,000 nodes, R = 6 relations. Indices int32.
//
// R2 showed LSU-issue-bound (L1 63%, issue 61%, L2 27%, DRAM 4%). This version
// packs 4 edges per warp (8 lanes/edge, 16 dims/lane) to amortize index loads
// (1 LDG per array per 4 edges), shuffles (3 per 4 edges instead of 5 per
// edge), and stores (1 STG.32 per 4 edges). Gather wavefronts are unchanged;
// per-edge LSU instruction count drops ~2.5x.

#define D        128
#define N_RELS   6
#define TPB      256                 // 8 warps = 32 edges per block
#define EDGES_PER_WARP  4
#define EDGES_PER_BLOCK (TPB / 32 * EDGES_PER_WARP)   // 32

__global__ __launch_bounds__(TPB) void distmult_kernel(
    const float* __restrict__ h,
    const float* __restrict__ W,
    const int* __restrict__ src,
    const int* __restrict__ dst,
    const int* __restrict__ rel,
    float* __restrict__ out,
    int E)
{
    __shared__ float sW[N_RELS * D];   // 3 KB

    for (int i = threadIdx.x; i < N_RELS * D; i += TPB)
        sW[i] = W[i];
    __syncthreads();

    const int warp_in_block = threadIdx.x >> 5;
    const int lane          = threadIdx.x & 31;
    const int sub           = lane >> 3;       // 8-lane group id: 0..3
    const int sl            = lane & 7;        // lane within group

    // Edge handled by this 8-lane group.
    const int e = (blockIdx.x * (TPB / 32) + warp_in_block) * EDGES_PER_WARP + sub;
    if (e >= E) return;                        // E % 4 == 0 here; whole groups drop

    // One broadcast-coalesced LDG.32 per array serves all 4 edges of the warp
    // (addresses span 16B). Streaming hint: don't evict h from L2.
    const int s = __ldcs(&src[e]);
    const int d = __ldcs(&dst[e]);
    const int r = __ldcs(&rel[e]);

    const float4* __restrict__ up = (const float4*)(h + (size_t)s * D);
    const float4* __restrict__ vp = (const float4*)(h + (size_t)d * D);
    const float4* __restrict__ wp = (const float4*)(sW + r * D);

    // 16 dims per lane: 4 chunks of float4, chunk k covers dims sl*4 + k*32.
    // Batch the global loads so they overlap (MLP), then FMA.
    float4 u0 = __ldg(up + sl);
    float4 u1 = __ldg(up + sl + 8);
    float4 u2 = __ldg(up + sl + 16);
    float4 u3 = __ldg(up + sl + 24);
    float4 v0 = __ldg(vp + sl);
    float4 v1 = __ldg(vp + sl + 8);
    float4 v2 = __ldg(vp + sl + 16);
    float4 v3 = __ldg(vp + sl + 24);
    float4 w0 = wp[sl];
    float4 w1 = wp[sl + 8];
    float4 w2 = wp[sl + 16];
    float4 w3 = wp[sl + 24];

    float acc;
    acc  = u0.x * w0.x * v0.x + u0.y * w0.y * v0.y
         + u0.z * w0.z * v0.z + u0.w * w0.w * v0.w;
    acc += u1.x * w1.x * v1.x + u1.y * w1.y * v1.y
         + u1.z * w1.z * v1.z + u1.w * w1.w * v1.w;
    acc += u2.x * w2.x * v2.x + u2.y * w2.y * v2.y
         + u2.z * w2.z * v2.z + u2.w * w2.w * v2.w;
    acc += u3.x * w3.x * v3.x + u3.y * w3.y * v3.y
         + u3.z * w3.z * v3.z + u3.w * w3.w * v3.w;

    // Reduce within each 8-lane group: xor offsets 4,2,1 stay inside the group.
    acc += __shfl_xor_sync(0xFFFFFFFFu, acc, 4);
    acc += __shfl_xor_sync(0xFFFFFFFFu, acc, 2);
    acc += __shfl_xor_sync(0xFFFFFFFFu, acc, 1);

    if (sl == 0) {
        float sig = 1.0f / (1.0f + __expf(-acc));
        __stcs(&out[e], sig);   // 4 lanes/warp write 4 consecutive floats
    }
}

extern "C" void kernel_launch(void* const* d_in, const int* in_sizes, int n_in,
                              void* d_out, int out_size)
{
    const float* h   = (const float*)d_in[0];
    const float* W   = (const float*)d_in[1];
    const int*   src = (const int*)d_in[2];
    const int*   dst = (const int*)d_in[3];
    const int*   rel = (const int*)d_in[4];
    float* out = (float*)d_out;

    const int E = in_sizes[2];
    const int blocks = (E + EDGES_PER_BLOCK - 1) / EDGES_PER_BLOCK;

    distmult_kernel<<<blocks, TPB>>>(h, W, src, dst, rel, out, E);
}

// round 4
// speedup vs baseline: 2.8089x; 1.3113x over previous
#include <cuda_runtime.h>
#include <cuda_bf16.h>
#include <cstdint>

// DistMult edge scoring:
//   out[e] = sigmoid( sum_d h[src[e]][d] * W[rel[e]][d] * h[dst[e]][d] )
// E = 1,500,000, D = 128, N = 100,000, R = 6. Indices int32.
//
// R3 was L1-port-bound (L1 73%, issue 42%) with 46.9K blocks each re-staging
// W (140 MB extra L2 traffic) and a cold index->gather dependency per quad.
// R4: persistent grid-stride warps (888 blocks), W staged once per block,
// next quad's indices prefetched under the current quad's gathers.
// Mapping unchanged: 4 edges/warp, 8 lanes/edge, 16 dims/lane.

#define D        128
#define N_RELS   6
#define TPB      256                 // 8 warps per block
#define NBLK     888                 // ~6 blocks per SM, persistent

__global__ __launch_bounds__(TPB) void distmult_kernel(
    const float* __restrict__ h,
    const float* __restrict__ W,
    const int* __restrict__ src,
    const int* __restrict__ dst,
    const int* __restrict__ rel,
    float* __restrict__ out,
    int E)
{
    __shared__ float sW[N_RELS * D];   // 3 KB, staged ONCE per block

    for (int i = threadIdx.x; i < N_RELS * D; i += TPB)
        sW[i] = W[i];
    __syncthreads();

    const int lane = threadIdx.x & 31;
    const int sub  = lane >> 3;        // 8-lane group: which of 4 edges
    const int sl   = lane & 7;         // lane within group: dim chunk

    const int n_warps = NBLK * (TPB / 32);                      // total warps
    const int gw      = blockIdx.x * (TPB / 32) + (threadIdx.x >> 5);
    const int Q       = E >> 2;        // number of edge-quads (E % 4 == 0)

    int q = gw;
    int s = 0, d = 0, r = 0;
    if (q < Q) {
        const int e = q * 4 + sub;
        s = __ldcs(&src[e]);           // one 16B broadcast segment per warp
        d = __ldcs(&dst[e]);
        r = __ldcs(&rel[e]);
    }

    while (q < Q) {
        const int e  = q * 4 + sub;
        const int qn = q + n_warps;

        const float4* __restrict__ up = (const float4*)(h + (size_t)s * D);
        const float4* __restrict__ vp = (const float4*)(h + (size_t)d * D);
        const float4* __restrict__ wp = (const float4*)(sW + r * D);

        // Batch all 8 gather loads first (max MLP, fully coalesced 128B lines).
        float4 u0 = __ldg(up + sl);
        float4 u1 = __ldg(up + sl + 8);
        float4 u2 = __ldg(up + sl + 16);
        float4 u3 = __ldg(up + sl + 24);
        float4 v0 = __ldg(vp + sl);
        float4 v1 = __ldg(vp + sl + 8);
        float4 v2 = __ldg(vp + sl + 16);
        float4 v3 = __ldg(vp + sl + 24);

        // Prefetch next quad's indices while gathers are in flight.
        int sn = 0, dn = 0, rn = 0;
        if (qn < Q) {
            const int en = qn * 4 + sub;
            sn = __ldcs(&src[en]);
            dn = __ldcs(&dst[en]);
            rn = __ldcs(&rel[en]);
        }

        // W from shared, consumed chunk-by-chunk to keep liveness low.
        // Phases are 8-lane groups reading 128B contiguous: conflict-free.
        float acc;
        {
            float4 w = wp[sl];
            acc  = u0.x * w.x * v0.x + u0.y * w.y * v0.y
                 + u0.z * w.z * v0.z + u0.w * w.w * v0.w;
        }
        {
            float4 w = wp[sl + 8];
            acc += u1.x * w.x * v1.x + u1.y * w.y * v1.y
                 + u1.z * w.z * v1.z + u1.w * w.w * v1.w;
        }
        {
            float4 w = wp[sl + 16];
            acc += u2.x * w.x * v2.x + u2.y * w.y * v2.y
                 + u2.z * w.z * v2.z + u2.w * w.w * v2.w;
        }
        {
            float4 w = wp[sl + 24];
            acc += u3.x * w.x * v3.x + u3.y * w.y * v3.y
                 + u3.z * w.z * v3.z + u3.w * w.w * v3.w;
        }

        // Reduce within the 8-lane group.
        acc += __shfl_xor_sync(0xFFFFFFFFu, acc, 4);
        acc += __shfl_xor_sync(0xFFFFFFFFu, acc, 2);
        acc += __shfl_xor_sync(0xFFFFFFFFu, acc, 1);

        if (sl == 0) {
            float sig = 1.0f / (1.0f + __expf(-acc));
            __stcs(&out[e], sig);      // 4 lanes/warp: 1 coalesced 16B segment
        }

        s = sn; d = dn; r = rn; q = qn;
    }
}

extern "C" void kernel_launch(void* const* d_in, const int* in_sizes, int n_in,
                              void* d_out, int out_size)
{
    const float* h   = (const float*)d_in[0];
    const float* W   = (const float*)d_in[1];
    const int*   src = (const int*)d_in[2];
    const int*   dst = (const int*)d_in[3];
    const int*   rel = (const int*)d_in[4];
    float* out = (float*)d_out;

    const int E = in_sizes[2];

    // Persistent grid; grid-stride loop handles any E / any SM count.
    int quads = E >> 2;
    int warps_needed = quads;                       // 1 quad per warp per iter
    int blocks = (warps_needed + (TPB / 32) - 1) / (TPB / 32);
    if (blocks > NBLK) blocks = NBLK;

    distmult_kernel<<<blocks, TPB>>>(h, W, src, dst, rel, out, E);
}